// round 16
// baseline (speedup 1.0000x reference)
#include <cuda_runtime.h>
#include <cuda_bf16.h>
#include <cstdint>

#define NODES_MAX 50000
#define F 128
#define CAP 96
#define OVF_MAX 65536

// Scratch (no runtime allocation allowed)
__device__ float g_P[NODES_MAX * F];        // h @ W1h^T + b1 (fp32, for gather)
__device__ float g_sums[NODES_MAX * F];     // overflow-path accumulation
__device__ int   g_cnt[NODES_MAX];          // in-degree
__device__ int   g_ovn;                     // overflow record count
__device__ __align__(16) int4 g_recs[NODES_MAX * CAP];  // {src, w0, w1, w2}
__device__ __align__(16) int4 g_ovf[OVF_MAX];
__device__ int   g_ovfd[OVF_MAX];
// bf16 hi/lo images (split once, consumed by copy-only GEMM staging):
__device__ __align__(16) unsigned short g_Hhi[NODES_MAX * F];
__device__ __align__(16) unsigned short g_Hlo[NODES_MAX * F];
__device__ __align__(16) unsigned short g_hNhi[NODES_MAX * F];
__device__ __align__(16) unsigned short g_hNlo[NODES_MAX * F];
__device__ __align__(16) unsigned short g_W1hi[128 * 128];
__device__ __align__(16) unsigned short g_W1lo[128 * 128];
__device__ __align__(16) unsigned short g_W2hi[128 * 256];
__device__ __align__(16) unsigned short g_W2lo[128 * 256];

__device__ __forceinline__ void split8(const float* f, uint32_t* ph, uint32_t* pl)
{
    #pragma unroll
    for (int q = 0; q < 4; q++) {
        __nv_bfloat16 h0 = __float2bfloat16(f[2 * q]);
        __nv_bfloat16 h1 = __float2bfloat16(f[2 * q + 1]);
        unsigned short l0 = __bfloat16_as_ushort(
            __float2bfloat16(f[2 * q] - __bfloat162float(h0)));
        unsigned short l1 = __bfloat16_as_ushort(
            __float2bfloat16(f[2 * q + 1] - __bfloat162float(h1)));
        ph[q] = (uint32_t)__bfloat16_as_ushort(h0) |
                ((uint32_t)__bfloat16_as_ushort(h1) << 16);
        pl[q] = (uint32_t)l0 | ((uint32_t)l1 << 16);
    }
}

// ---------------------------------------------------------------------------
// Prep: split weights AND h into bf16 hi/lo; zero counters + overflow acc
// ---------------------------------------------------------------------------
__global__ void prep_kernel(const float* __restrict__ W1,
                            const float* __restrict__ W2,
                            const float* __restrict__ hin, int n_nodes)
{
    int idx = blockIdx.x * blockDim.x + threadIdx.x;
    int stride = gridDim.x * blockDim.x;

    if (idx == 0) g_ovn = 0;
    for (int i = idx; i < 128 * 128; i += stride) {
        int n = i >> 7, k = i & 127;
        float w = W1[n * 131 + k];
        __nv_bfloat16 h = __float2bfloat16(w);
        g_W1hi[i] = __bfloat16_as_ushort(h);
        g_W1lo[i] = __bfloat16_as_ushort(__float2bfloat16(w - __bfloat162float(h)));
    }
    for (int i = idx; i < 128 * 256; i += stride) {
        float w = W2[i];
        __nv_bfloat16 h = __float2bfloat16(w);
        g_W2hi[i] = __bfloat16_as_ushort(h);
        g_W2lo[i] = __bfloat16_as_ushort(__float2bfloat16(w - __bfloat162float(h)));
    }
    // h split: 8 floats per iteration -> one uint4 hi + one uint4 lo
    for (int i = idx; i < n_nodes * 16; i += stride) {
        float4 a = ((const float4*)hin)[i * 2];
        float4 b = ((const float4*)hin)[i * 2 + 1];
        float f[8] = {a.x, a.y, a.z, a.w, b.x, b.y, b.z, b.w};
        uint32_t ph[4], pl[4];
        split8(f, ph, pl);
        ((uint4*)g_Hhi)[i] = make_uint4(ph[0], ph[1], ph[2], ph[3]);
        ((uint4*)g_Hlo)[i] = make_uint4(pl[0], pl[1], pl[2], pl[3]);
    }
    int nsum4 = (n_nodes * F) >> 2;
    float4* s4 = reinterpret_cast<float4*>(g_sums);
    float4 z = make_float4(0.f, 0.f, 0.f, 0.f);
    for (int i = idx; i < nsum4; i += stride) s4[i] = z;
    for (int i = idx; i < n_nodes; i += stride) g_cnt[i] = 0;
}

// ---------------------------------------------------------------------------
// Scatter: thread per edge; bucket record under dst (overflow -> side list)
// ---------------------------------------------------------------------------
__global__ void scatter_kernel(const int* __restrict__ src,
                               const int* __restrict__ dst,
                               const float* __restrict__ ew, int E)
{
    int e = blockIdx.x * blockDim.x + threadIdx.x;
    if (e >= E) return;
    int d = dst[e];
    int pos = atomicAdd(&g_cnt[d], 1);
    int4 r;
    r.x = src[e];
    r.y = __float_as_int(ew[e * 3 + 0]);
    r.z = __float_as_int(ew[e * 3 + 1]);
    r.w = __float_as_int(ew[e * 3 + 2]);
    if (pos < CAP) {
        g_recs[d * CAP + pos] = r;
    } else {
        int o = atomicAdd(&g_ovn, 1);
        if (o < OVF_MAX) { g_ovf[o] = r; g_ovfd[o] = d; }
    }
}

// ---------------------------------------------------------------------------
// Overflow: early-exit, then warp per spilled edge into zeroed g_sums
// ---------------------------------------------------------------------------
__global__ __launch_bounds__(256) void overflow_kernel(const float* __restrict__ W1)
{
    const int n = g_ovn;
    if (n == 0) return;

    __shared__ float cw[3][128];
    for (int i = threadIdx.x; i < 384; i += 256) {
        int t = i >> 7, j = i & 127;
        cw[t][j] = W1[j * 131 + 128 + t];
    }
    __syncthreads();

    const int lane = threadIdx.x & 31;
    const int col  = lane * 4;
    const float4 cA = *(const float4*)&cw[0][col];
    const float4 cB = *(const float4*)&cw[1][col];
    const float4 cC = *(const float4*)&cw[2][col];

    for (int e = (threadIdx.x >> 5); e < n && e < OVF_MAX; e += 8) {
        int4 r = g_ovf[e];
        int d = g_ovfd[e];
        float w0 = __int_as_float(r.y), w1 = __int_as_float(r.z),
              w2 = __int_as_float(r.w);
        float4 p = *(const float4*)(g_P + (long)r.x * 128 + col);
        float t0 = p.x + w0 * cA.x + w1 * cB.x + w2 * cC.x;
        float t1 = p.y + w0 * cA.y + w1 * cB.y + w2 * cC.y;
        float t2 = p.z + w0 * cA.z + w1 * cB.z + w2 * cC.z;
        float t3 = p.w + w0 * cA.w + w1 * cB.w + w2 * cC.w;
        t0 = (t0 < 0.f) ? 0.01f * t0 : t0;
        t1 = (t1 < 0.f) ? 0.01f * t1 : t1;
        t2 = (t2 < 0.f) ? 0.01f * t2 : t2;
        t3 = (t3 < 0.f) ? 0.01f * t3 : t3;
        float* addr = g_sums + (long)d * 128 + col;
        asm volatile("red.global.add.v4.f32 [%0], {%1, %2, %3, %4};"
                     :: "l"(addr), "f"(t0), "f"(t1), "f"(t2), "f"(t3)
                     : "memory");
    }
}

// ---------------------------------------------------------------------------
// Aggregate: warp per node; register accumulation; writes hN as bf16 hi/lo
// ---------------------------------------------------------------------------
__device__ __forceinline__ void edge_accum(
    float4& acc, float4 p, float w0, float w1, float w2,
    float4 cA, float4 cB, float4 cC)
{
    float t0 = p.x + w0 * cA.x + w1 * cB.x + w2 * cC.x;
    float t1 = p.y + w0 * cA.y + w1 * cB.y + w2 * cC.y;
    float t2 = p.z + w0 * cA.z + w1 * cB.z + w2 * cC.z;
    float t3 = p.w + w0 * cA.w + w1 * cB.w + w2 * cC.w;
    acc.x += (t0 < 0.f) ? 0.01f * t0 : t0;
    acc.y += (t1 < 0.f) ? 0.01f * t1 : t1;
    acc.z += (t2 < 0.f) ? 0.01f * t2 : t2;
    acc.w += (t3 < 0.f) ? 0.01f * t3 : t3;
}

__global__ __launch_bounds__(256) void aggregate_kernel(
    const float* __restrict__ W1, int M)
{
    __shared__ float cw[3][128];
    for (int i = threadIdx.x; i < 384; i += 256) {
        int t = i >> 7, j = i & 127;
        cw[t][j] = W1[j * 131 + 128 + t];
    }
    __syncthreads();

    const int node = blockIdx.x * 8 + (threadIdx.x >> 5);
    if (node >= M) return;
    const int lane = threadIdx.x & 31;
    const int col  = lane * 4;
    const float4 cA = *(const float4*)&cw[0][col];
    const float4 cB = *(const float4*)&cw[1][col];
    const float4 cC = *(const float4*)&cw[2][col];

    const int deg  = g_cnt[node];
    const int nrec = (deg < CAP) ? deg : CAP;
    const long base = (long)node * CAP;

    float4 acc = make_float4(0.f, 0.f, 0.f, 0.f);
    int e = 0;
    for (; e + 4 <= nrec; e += 4) {
        int4 r0 = g_recs[base + e + 0];
        int4 r1 = g_recs[base + e + 1];
        int4 r2 = g_recs[base + e + 2];
        int4 r3 = g_recs[base + e + 3];
        float4 p0 = *(const float4*)(g_P + (long)r0.x * 128 + col);
        float4 p1 = *(const float4*)(g_P + (long)r1.x * 128 + col);
        float4 p2 = *(const float4*)(g_P + (long)r2.x * 128 + col);
        float4 p3 = *(const float4*)(g_P + (long)r3.x * 128 + col);
        edge_accum(acc, p0, __int_as_float(r0.y), __int_as_float(r0.z),
                   __int_as_float(r0.w), cA, cB, cC);
        edge_accum(acc, p1, __int_as_float(r1.y), __int_as_float(r1.z),
                   __int_as_float(r1.w), cA, cB, cC);
        edge_accum(acc, p2, __int_as_float(r2.y), __int_as_float(r2.z),
                   __int_as_float(r2.w), cA, cB, cC);
        edge_accum(acc, p3, __int_as_float(r3.y), __int_as_float(r3.z),
                   __int_as_float(r3.w), cA, cB, cC);
    }
    for (; e < nrec; e++) {
        int4 r0 = g_recs[base + e];
        float4 p0 = *(const float4*)(g_P + (long)r0.x * 128 + col);
        edge_accum(acc, p0, __int_as_float(r0.y), __int_as_float(r0.z),
                   __int_as_float(r0.w), cA, cB, cC);
    }
    if (deg > CAP) {   // fold in overflow-path accumulation
        float4 s = *(const float4*)(g_sums + (long)node * 128 + col);
        acc.x += s.x; acc.y += s.y; acc.z += s.z; acc.w += s.w;
    }

    float inv = (deg > 0) ? (1.0f / (float)deg) : 0.0f;
    float m[4] = {acc.x * inv, acc.y * inv, acc.z * inv, acc.w * inv};

    // split mean to bf16 hi/lo and store (8B per lane each)
    uint32_t ph[2], pl[2];
    #pragma unroll
    for (int q = 0; q < 2; q++) {
        __nv_bfloat16 h0 = __float2bfloat16(m[2 * q]);
        __nv_bfloat16 h1 = __float2bfloat16(m[2 * q + 1]);
        unsigned short l0 = __bfloat16_as_ushort(
            __float2bfloat16(m[2 * q] - __bfloat162float(h0)));
        unsigned short l1 = __bfloat16_as_ushort(
            __float2bfloat16(m[2 * q + 1] - __bfloat162float(h1)));
        ph[q] = (uint32_t)__bfloat16_as_ushort(h0) |
                ((uint32_t)__bfloat16_as_ushort(h1) << 16);
        pl[q] = (uint32_t)l0 | ((uint32_t)l1 << 16);
    }
    *(uint2*)&g_hNhi[(long)node * 128 + col] = make_uint2(ph[0], ph[1]);
    *(uint2*)&g_hNlo[(long)node * 128 + col] = make_uint2(pl[0], pl[1]);
}

// ---------------------------------------------------------------------------
// mma.sync m16n8k16 bf16 (A row, B col), fp32 accumulate
// ---------------------------------------------------------------------------
__device__ __forceinline__ void mma_bf16(float c[4], const uint32_t a[4],
                                         const uint32_t b[2])
{
    asm volatile(
        "mma.sync.aligned.m16n8k16.row.col.f32.bf16.bf16.f32 "
        "{%0,%1,%2,%3}, {%4,%5,%6,%7}, {%8,%9}, {%0,%1,%2,%3};"
        : "+f"(c[0]), "+f"(c[1]), "+f"(c[2]), "+f"(c[3])
        : "r"(a[0]), "r"(a[1]), "r"(a[2]), "r"(a[3]), "r"(b[0]), "r"(b[1]));
}

// ---------------------------------------------------------------------------
// Tensor-core GEMM (HMMA, bf16x3), copy-only staging (pre-split images),
// 2 CTAs/SM. WSEL=1: A=g_H (K=128), B=g_W1, out=g_P (fp32).
// WSEL=2: A=[g_H | g_hN] (K=256), B=g_W2, out=arg with relu.
// ---------------------------------------------------------------------------
#define KS_STRIDE 40

template<int KTOT, bool RELU, int WSEL>
__global__ __launch_bounds__(256, 2) void gemm_mma_kernel(
    const float* __restrict__ bias, float* __restrict__ out_arg, int M)
{
    const unsigned short* __restrict__ Bhi_g = (WSEL == 1) ? g_W1hi : g_W2hi;
    const unsigned short* __restrict__ Blo_g = (WSEL == 1) ? g_W1lo : g_W2lo;
    float* __restrict__ out = (WSEL == 1) ? g_P : out_arg;

    __shared__ __align__(16) unsigned short sAhi[128 * KS_STRIDE];
    __shared__ __align__(16) unsigned short sAlo[128 * KS_STRIDE];
    __shared__ __align__(16) unsigned short sBhi[128 * KS_STRIDE];
    __shared__ __align__(16) unsigned short sBlo[128 * KS_STRIDE];

    const int tid = threadIdx.x;
    const int row0 = blockIdx.x * 128;
    const int wid = tid >> 5, lane = tid & 31;
    const int wm = wid >> 2, wn = wid & 3;
    const int g = lane >> 2, t4 = lane & 3;

    const int srow = tid >> 1;
    const int skh = (tid & 1) * 16;
    const int grow = row0 + srow;
    const bool rowok = grow < M;

    float acc[4][4][4];
    #pragma unroll
    for (int i = 0; i < 4; i++)
        #pragma unroll
        for (int j = 0; j < 4; j++)
            #pragma unroll
            for (int q = 0; q < 4; q++) acc[i][j][q] = 0.f;

    #pragma unroll 1
    for (int k0 = 0; k0 < KTOT; k0 += 32) {
        // ---- stage A: pure copy of pre-split images ----
        {
            uint4 vh0 = make_uint4(0, 0, 0, 0), vh1 = vh0, vl0 = vh0, vl1 = vh0;
            if (rowok) {
                const bool second = (KTOT == 256) && (k0 >= 128);
                const unsigned short* ah = second
                    ? (g_hNhi + (long)grow * 128 + (k0 - 128) + skh)
                    : (g_Hhi + (long)grow * 128 + k0 + skh);
                const unsigned short* al = second
                    ? (g_hNlo + (long)grow * 128 + (k0 - 128) + skh)
                    : (g_Hlo + (long)grow * 128 + k0 + skh);
                vh0 = *(const uint4*)ah; vh1 = *(const uint4*)(ah + 8);
                vl0 = *(const uint4*)al; vl1 = *(const uint4*)(al + 8);
            }
            uint4* dh = (uint4*)&sAhi[srow * KS_STRIDE + skh];
            uint4* dl = (uint4*)&sAlo[srow * KS_STRIDE + skh];
            dh[0] = vh0; dh[1] = vh1;
            dl[0] = vl0; dl[1] = vl1;
        }
        // ---- stage B: straight copy of pre-split images ----
        {
            const unsigned short* bh = Bhi_g + (long)srow * KTOT + k0 + skh;
            const unsigned short* bl = Blo_g + (long)srow * KTOT + k0 + skh;
            uint4* dh = (uint4*)&sBhi[srow * KS_STRIDE + skh];
            uint4* dl = (uint4*)&sBlo[srow * KS_STRIDE + skh];
            dh[0] = *(const uint4*)bh; dh[1] = *(const uint4*)(bh + 8);
            dl[0] = *(const uint4*)bl; dl[1] = *(const uint4*)(bl + 8);
        }
        __syncthreads();

        #pragma unroll
        for (int ks = 0; ks < 32; ks += 16) {
            uint32_t ah[4][4], al[4][4];
            #pragma unroll
            for (int mt = 0; mt < 4; mt++) {
                int o = (wm * 64 + mt * 16 + g) * KS_STRIDE + ks + t4 * 2;
                ah[mt][0] = *(const uint32_t*)&sAhi[o];
                ah[mt][1] = *(const uint32_t*)&sAhi[o + 8 * KS_STRIDE];
                ah[mt][2] = *(const uint32_t*)&sAhi[o + 8];
                ah[mt][3] = *(const uint32_t*)&sAhi[o + 8 * KS_STRIDE + 8];
                al[mt][0] = *(const uint32_t*)&sAlo[o];
                al[mt][1] = *(const uint32_t*)&sAlo[o + 8 * KS_STRIDE];
                al[mt][2] = *(const uint32_t*)&sAlo[o + 8];
                al[mt][3] = *(const uint32_t*)&sAlo[o + 8 * KS_STRIDE + 8];
            }
            uint32_t bh[4][2], bl[4][2];
            #pragma unroll
            for (int nt = 0; nt < 4; nt++) {
                int o = (wn * 32 + nt * 8 + g) * KS_STRIDE + ks + t4 * 2;
                bh[nt][0] = *(const uint32_t*)&sBhi[o];
                bh[nt][1] = *(const uint32_t*)&sBhi[o + 8];
                bl[nt][0] = *(const uint32_t*)&sBlo[o];
                bl[nt][1] = *(const uint32_t*)&sBlo[o + 8];
            }
            #pragma unroll
            for (int mt = 0; mt < 4; mt++)
                #pragma unroll
                for (int nt = 0; nt < 4; nt++) {
                    mma_bf16(acc[mt][nt], ah[mt], bh[nt]);
                    mma_bf16(acc[mt][nt], ah[mt], bl[nt]);
                    mma_bf16(acc[mt][nt], al[mt], bh[nt]);
                }
        }
        __syncthreads();
    }

    // ---- epilogue ----
    #pragma unroll
    for (int mt = 0; mt < 4; mt++) {
        int r0_ = row0 + wm * 64 + mt * 16 + g;
        int r1_ = r0_ + 8;
        #pragma unroll
        for (int nt = 0; nt < 4; nt++) {
            int c = wn * 32 + nt * 8 + t4 * 2;
            float b0 = bias[c], b1 = bias[c + 1];
            float v0 = acc[mt][nt][0] + b0, v1 = acc[mt][nt][1] + b1;
            float v2 = acc[mt][nt][2] + b0, v3 = acc[mt][nt][3] + b1;
            if (RELU) {
                v0 = fmaxf(v0, 0.f); v1 = fmaxf(v1, 0.f);
                v2 = fmaxf(v2, 0.f); v3 = fmaxf(v3, 0.f);
            }
            if (r0_ < M) *(float2*)(out + (long)r0_ * 128 + c) = make_float2(v0, v1);
            if (r1_ < M) *(float2*)(out + (long)r1_ * 128 + c) = make_float2(v2, v3);
        }
    }
}

// ---------------------------------------------------------------------------
extern "C" void kernel_launch(void* const* d_in, const int* in_sizes, int n_in,
                              void* d_out, int out_size)
{
    const float* h    = (const float*)d_in[0];
    const int*   esrc = (const int*)  d_in[1];
    const int*   edst = (const int*)  d_in[2];
    const float* ew   = (const float*)d_in[3];
    const float* W1   = (const float*)d_in[4];
    const float* b1   = (const float*)d_in[5];
    const float* W2   = (const float*)d_in[6];
    const float* b2   = (const float*)d_in[7];
    float* out = (float*)d_out;

    int M = in_sizes[0] / 128;    // 50000 nodes
    int E = in_sizes[1];          // 800000 edges
    int nT = (M + 127) / 128;     // 391 row tiles

    prep_kernel<<<592, 256>>>(W1, W2, h, M);
    scatter_kernel<<<(E + 255) / 256, 256>>>(esrc, edst, ew, E);
    gemm_mma_kernel<128, false, 1><<<nT, 256>>>(b1, nullptr, M);
    overflow_kernel<<<1, 256>>>(W1);
    aggregate_kernel<<<(M + 7) / 8, 256>>>(W1, M);
    gemm_mma_kernel<256, true, 2><<<nT, 256>>>(b2, out, M);
}

// round 17
// speedup vs baseline: 1.0809x; 1.0809x over previous
#include <cuda_runtime.h>
#include <cuda_bf16.h>
#include <cstdint>

#define NODES_MAX 50000
#define F 128
#define CAP 96
#define OVF_MAX 65536

// Scratch (no runtime allocation allowed)
__device__ float g_P[NODES_MAX * F];        // h @ W1h^T + b1
__device__ float g_hN[NODES_MAX * F];       // per-node mean message
__device__ int   g_cnt[NODES_MAX];          // in-degree (int)
__device__ int   g_ovn;                     // overflow record count
__device__ __align__(16) int4 g_recs[NODES_MAX * CAP];  // {src, w0, w1, w2}
__device__ __align__(16) int4 g_ovf[OVF_MAX];
__device__ int   g_ovfd[OVF_MAX];
__device__ __align__(16) unsigned short g_W1hi[128 * 128];  // [n][k] bf16 hi
__device__ __align__(16) unsigned short g_W1lo[128 * 128];
__device__ __align__(16) unsigned short g_W2hi[128 * 256];
__device__ __align__(16) unsigned short g_W2lo[128 * 256];

// ---------------------------------------------------------------------------
// Prep: bf16 hi/lo weight splits, zero counters
// ---------------------------------------------------------------------------
__global__ void prep_kernel(const float* __restrict__ W1,
                            const float* __restrict__ W2, int n_nodes)
{
    int idx = blockIdx.x * blockDim.x + threadIdx.x;
    int stride = gridDim.x * blockDim.x;

    if (idx == 0) g_ovn = 0;
    for (int i = idx; i < 128 * 128; i += stride) {
        int n = i >> 7, k = i & 127;
        float w = W1[n * 131 + k];
        __nv_bfloat16 h = __float2bfloat16(w);
        g_W1hi[i] = __bfloat16_as_ushort(h);
        g_W1lo[i] = __bfloat16_as_ushort(__float2bfloat16(w - __bfloat162float(h)));
    }
    for (int i = idx; i < 128 * 256; i += stride) {
        float w = W2[i];
        __nv_bfloat16 h = __float2bfloat16(w);
        g_W2hi[i] = __bfloat16_as_ushort(h);
        g_W2lo[i] = __bfloat16_as_ushort(__float2bfloat16(w - __bfloat162float(h)));
    }
    for (int i = idx; i < n_nodes; i += stride) g_cnt[i] = 0;
}

// ---------------------------------------------------------------------------
// Scatter: thread per edge; bucket record under dst (overflow -> side list)
// ---------------------------------------------------------------------------
__global__ void scatter_kernel(const int* __restrict__ src,
                               const int* __restrict__ dst,
                               const float* __restrict__ ew, int E)
{
    int e = blockIdx.x * blockDim.x + threadIdx.x;
    if (e >= E) return;
    int d = dst[e];
    int pos = atomicAdd(&g_cnt[d], 1);
    int4 r;
    r.x = src[e];
    r.y = __float_as_int(ew[e * 3 + 0]);
    r.z = __float_as_int(ew[e * 3 + 1]);
    r.w = __float_as_int(ew[e * 3 + 2]);
    if (pos < CAP) {
        g_recs[d * CAP + pos] = r;
    } else {
        int o = atomicAdd(&g_ovn, 1);
        if (o < OVF_MAX) { g_ovf[o] = r; g_ovfd[o] = d; }
    }
}

// ---------------------------------------------------------------------------
// Aggregate: warp per node; unroll-4 register accumulation, one mean write.
// Nodes with deg > CAP additionally scan the (normally empty) overflow list.
// ---------------------------------------------------------------------------
__device__ __forceinline__ void edge_accum(
    float4& acc, float4 p, float w0, float w1, float w2,
    float4 cA, float4 cB, float4 cC)
{
    float t0 = p.x + w0 * cA.x + w1 * cB.x + w2 * cC.x;
    float t1 = p.y + w0 * cA.y + w1 * cB.y + w2 * cC.y;
    float t2 = p.z + w0 * cA.z + w1 * cB.z + w2 * cC.z;
    float t3 = p.w + w0 * cA.w + w1 * cB.w + w2 * cC.w;
    acc.x += (t0 < 0.f) ? 0.01f * t0 : t0;
    acc.y += (t1 < 0.f) ? 0.01f * t1 : t1;
    acc.z += (t2 < 0.f) ? 0.01f * t2 : t2;
    acc.w += (t3 < 0.f) ? 0.01f * t3 : t3;
}

__global__ __launch_bounds__(256) void aggregate_kernel(
    const float* __restrict__ W1, int M)
{
    __shared__ float cw[3][128];
    for (int i = threadIdx.x; i < 384; i += 256) {
        int t = i >> 7, j = i & 127;
        cw[t][j] = W1[j * 131 + 128 + t];
    }
    __syncthreads();

    const int node = blockIdx.x * 8 + (threadIdx.x >> 5);
    if (node >= M) return;
    const int lane = threadIdx.x & 31;
    const int col  = lane * 4;
    const float4 cA = *(const float4*)&cw[0][col];
    const float4 cB = *(const float4*)&cw[1][col];
    const float4 cC = *(const float4*)&cw[2][col];

    const int deg  = g_cnt[node];
    const int nrec = (deg < CAP) ? deg : CAP;
    const long base = (long)node * CAP;

    float4 acc = make_float4(0.f, 0.f, 0.f, 0.f);
    int e = 0;
    for (; e + 4 <= nrec; e += 4) {
        int4 r0 = g_recs[base + e + 0];
        int4 r1 = g_recs[base + e + 1];
        int4 r2 = g_recs[base + e + 2];
        int4 r3 = g_recs[base + e + 3];
        float4 p0 = *(const float4*)(g_P + (long)r0.x * 128 + col);
        float4 p1 = *(const float4*)(g_P + (long)r1.x * 128 + col);
        float4 p2 = *(const float4*)(g_P + (long)r2.x * 128 + col);
        float4 p3 = *(const float4*)(g_P + (long)r3.x * 128 + col);
        edge_accum(acc, p0, __int_as_float(r0.y), __int_as_float(r0.z),
                   __int_as_float(r0.w), cA, cB, cC);
        edge_accum(acc, p1, __int_as_float(r1.y), __int_as_float(r1.z),
                   __int_as_float(r1.w), cA, cB, cC);
        edge_accum(acc, p2, __int_as_float(r2.y), __int_as_float(r2.z),
                   __int_as_float(r2.w), cA, cB, cC);
        edge_accum(acc, p3, __int_as_float(r3.y), __int_as_float(r3.z),
                   __int_as_float(r3.w), cA, cB, cC);
    }
    for (; e < nrec; e++) {
        int4 r0 = g_recs[base + e];
        float4 p0 = *(const float4*)(g_P + (long)r0.x * 128 + col);
        edge_accum(acc, p0, __int_as_float(r0.y), __int_as_float(r0.z),
                   __int_as_float(r0.w), cA, cB, cC);
    }
    if (deg > CAP) {   // inline overflow scan (normally ovn == 0)
        int n = g_ovn;
        if (n > OVF_MAX) n = OVF_MAX;
        for (int o = 0; o < n; o++) {
            if (g_ovfd[o] == node) {
                int4 r0 = g_ovf[o];
                float4 p0 = *(const float4*)(g_P + (long)r0.x * 128 + col);
                edge_accum(acc, p0, __int_as_float(r0.y), __int_as_float(r0.z),
                           __int_as_float(r0.w), cA, cB, cC);
            }
        }
    }

    float inv = (deg > 0) ? (1.0f / (float)deg) : 0.0f;
    float4 o = make_float4(acc.x * inv, acc.y * inv, acc.z * inv, acc.w * inv);
    *(float4*)(g_hN + (long)node * 128 + col) = o;
}

// ---------------------------------------------------------------------------
// mma.sync m16n8k16 bf16 (A row, B col), fp32 accumulate
// ---------------------------------------------------------------------------
__device__ __forceinline__ void mma_bf16(float c[4], const uint32_t a[4],
                                         const uint32_t b[2])
{
    asm volatile(
        "mma.sync.aligned.m16n8k16.row.col.f32.bf16.bf16.f32 "
        "{%0,%1,%2,%3}, {%4,%5,%6,%7}, {%8,%9}, {%0,%1,%2,%3};"
        : "+f"(c[0]), "+f"(c[1]), "+f"(c[2]), "+f"(c[3])
        : "r"(a[0]), "r"(a[1]), "r"(a[2]), "r"(a[3]), "r"(b[0]), "r"(b[1]));
}

// ---------------------------------------------------------------------------
// Tensor-core GEMM (HMMA, bf16x3), 2 CTAs/SM (proven r14/r15 build).
// WSEL=1: B=g_W1 (KTOT=128), out=g_P. WSEL=2: B=g_W2 (KTOT=256),
// A k>=128 from g_hN (mean pre-applied), out=arg.
// ---------------------------------------------------------------------------
#define KS_STRIDE 40

template<int KTOT, bool RELU, int WSEL>
__global__ __launch_bounds__(256, 2) void gemm_mma_kernel(
    const float* __restrict__ A1, const float* __restrict__ bias,
    float* __restrict__ out_arg, int M)
{
    const unsigned short* __restrict__ Bhi_g = (WSEL == 1) ? g_W1hi : g_W2hi;
    const unsigned short* __restrict__ Blo_g = (WSEL == 1) ? g_W1lo : g_W2lo;
    const float* __restrict__ A2 = g_hN;
    float* __restrict__ out = (WSEL == 1) ? g_P : out_arg;

    __shared__ __align__(16) unsigned short sAhi[128 * KS_STRIDE];
    __shared__ __align__(16) unsigned short sAlo[128 * KS_STRIDE];
    __shared__ __align__(16) unsigned short sBhi[128 * KS_STRIDE];
    __shared__ __align__(16) unsigned short sBlo[128 * KS_STRIDE];

    const int tid = threadIdx.x;
    const int row0 = blockIdx.x * 128;
    const int wid = tid >> 5, lane = tid & 31;
    const int wm = wid >> 2, wn = wid & 3;
    const int g = lane >> 2, t4 = lane & 3;

    const int srow = tid >> 1;
    const int skh = (tid & 1) * 16;
    const int grow = row0 + srow;
    const bool rowok = grow < M;

    float acc[4][4][4];
    #pragma unroll
    for (int i = 0; i < 4; i++)
        #pragma unroll
        for (int j = 0; j < 4; j++)
            #pragma unroll
            for (int q = 0; q < 4; q++) acc[i][j][q] = 0.f;

    #pragma unroll 1
    for (int k0 = 0; k0 < KTOT; k0 += 32) {
        // ---- stage A: fp32 -> bf16 hi/lo into padded smem ----
        {
            float f[16];
            #pragma unroll
            for (int q = 0; q < 16; q++) f[q] = 0.f;
            if (rowok) {
                const bool second = (KTOT == 256) && (k0 >= 128);
                const float* src = second
                    ? (A2 + (long)grow * 128 + (k0 - 128) + skh)
                    : (A1 + (long)grow * 128 + k0 + skh);
                #pragma unroll
                for (int q = 0; q < 4; q++) {
                    float4 v = *(const float4*)(src + q * 4);
                    f[q * 4 + 0] = v.x; f[q * 4 + 1] = v.y;
                    f[q * 4 + 2] = v.z; f[q * 4 + 3] = v.w;
                }
            }
            uint32_t ph[8], pl[8];
            #pragma unroll
            for (int q = 0; q < 8; q++) {
                __nv_bfloat16 h0 = __float2bfloat16(f[2 * q]);
                __nv_bfloat16 h1 = __float2bfloat16(f[2 * q + 1]);
                unsigned short l0 = __bfloat16_as_ushort(
                    __float2bfloat16(f[2 * q] - __bfloat162float(h0)));
                unsigned short l1 = __bfloat16_as_ushort(
                    __float2bfloat16(f[2 * q + 1] - __bfloat162float(h1)));
                ph[q] = (uint32_t)__bfloat16_as_ushort(h0) |
                        ((uint32_t)__bfloat16_as_ushort(h1) << 16);
                pl[q] = (uint32_t)l0 | ((uint32_t)l1 << 16);
            }
            uint4* dh = (uint4*)&sAhi[srow * KS_STRIDE + skh];
            uint4* dl = (uint4*)&sAlo[srow * KS_STRIDE + skh];
            dh[0] = make_uint4(ph[0], ph[1], ph[2], ph[3]);
            dh[1] = make_uint4(ph[4], ph[5], ph[6], ph[7]);
            dl[0] = make_uint4(pl[0], pl[1], pl[2], pl[3]);
            dl[1] = make_uint4(pl[4], pl[5], pl[6], pl[7]);
        }
        // ---- stage B: straight copy of pre-split images ----
        {
            const unsigned short* bh = Bhi_g + (long)srow * KTOT + k0 + skh;
            const unsigned short* bl = Blo_g + (long)srow * KTOT + k0 + skh;
            uint4* dh = (uint4*)&sBhi[srow * KS_STRIDE + skh];
            uint4* dl = (uint4*)&sBlo[srow * KS_STRIDE + skh];
            dh[0] = *(const uint4*)bh; dh[1] = *(const uint4*)(bh + 8);
            dl[0] = *(const uint4*)bl; dl[1] = *(const uint4*)(bl + 8);
        }
        __syncthreads();

        #pragma unroll
        for (int ks = 0; ks < 32; ks += 16) {
            uint32_t ah[4][4], al[4][4];
            #pragma unroll
            for (int mt = 0; mt < 4; mt++) {
                int o = (wm * 64 + mt * 16 + g) * KS_STRIDE + ks + t4 * 2;
                ah[mt][0] = *(const uint32_t*)&sAhi[o];
                ah[mt][1] = *(const uint32_t*)&sAhi[o + 8 * KS_STRIDE];
                ah[mt][2] = *(const uint32_t*)&sAhi[o + 8];
                ah[mt][3] = *(const uint32_t*)&sAhi[o + 8 * KS_STRIDE + 8];
                al[mt][0] = *(const uint32_t*)&sAlo[o];
                al[mt][1] = *(const uint32_t*)&sAlo[o + 8 * KS_STRIDE];
                al[mt][2] = *(const uint32_t*)&sAlo[o + 8];
                al[mt][3] = *(const uint32_t*)&sAlo[o + 8 * KS_STRIDE + 8];
            }
            uint32_t bh[4][2], bl[4][2];
            #pragma unroll
            for (int nt = 0; nt < 4; nt++) {
                int o = (wn * 32 + nt * 8 + g) * KS_STRIDE + ks + t4 * 2;
                bh[nt][0] = *(const uint32_t*)&sBhi[o];
                bh[nt][1] = *(const uint32_t*)&sBhi[o + 8];
                bl[nt][0] = *(const uint32_t*)&sBlo[o];
                bl[nt][1] = *(const uint32_t*)&sBlo[o + 8];
            }
            #pragma unroll
            for (int mt = 0; mt < 4; mt++)
                #pragma unroll
                for (int nt = 0; nt < 4; nt++) {
                    mma_bf16(acc[mt][nt], ah[mt], bh[nt]);
                    mma_bf16(acc[mt][nt], ah[mt], bl[nt]);
                    mma_bf16(acc[mt][nt], al[mt], bh[nt]);
                }
        }
        __syncthreads();
    }

    // ---- epilogue ----
    #pragma unroll
    for (int mt = 0; mt < 4; mt++) {
        int r0_ = row0 + wm * 64 + mt * 16 + g;
        int r1_ = r0_ + 8;
        #pragma unroll
        for (int nt = 0; nt < 4; nt++) {
            int c = wn * 32 + nt * 8 + t4 * 2;
            float b0 = bias[c], b1 = bias[c + 1];
            float v0 = acc[mt][nt][0] + b0, v1 = acc[mt][nt][1] + b1;
            float v2 = acc[mt][nt][2] + b0, v3 = acc[mt][nt][3] + b1;
            if (RELU) {
                v0 = fmaxf(v0, 0.f); v1 = fmaxf(v1, 0.f);
                v2 = fmaxf(v2, 0.f); v3 = fmaxf(v3, 0.f);
            }
            if (r0_ < M) *(float2*)(out + (long)r0_ * 128 + c) = make_float2(v0, v1);
            if (r1_ < M) *(float2*)(out + (long)r1_ * 128 + c) = make_float2(v2, v3);
        }
    }
}

// ---------------------------------------------------------------------------
extern "C" void kernel_launch(void* const* d_in, const int* in_sizes, int n_in,
                              void* d_out, int out_size)
{
    const float* h    = (const float*)d_in[0];
    const int*   esrc = (const int*)  d_in[1];
    const int*   edst = (const int*)  d_in[2];
    const float* ew   = (const float*)d_in[3];
    const float* W1   = (const float*)d_in[4];
    const float* b1   = (const float*)d_in[5];
    const float* W2   = (const float*)d_in[6];
    const float* b2   = (const float*)d_in[7];
    float* out = (float*)d_out;

    int M = in_sizes[0] / 128;    // 50000 nodes
    int E = in_sizes[1];          // 800000 edges
    int nT = (M + 127) / 128;     // 391 row tiles

    prep_kernel<<<512, 256>>>(W1, W2, M);
    scatter_kernel<<<(E + 255) / 256, 256>>>(esrc, edst, ew, E);
    gemm_mma_kernel<128, false, 1><<<nT, 256>>>(h, b1, nullptr, M);
    aggregate_kernel<<<(M + 7) / 8, 256>>>(W1, M);
    gemm_mma_kernel<256, true, 2><<<nT, 256>>>(h, b2, out, M);
}